// round 1
// baseline (speedup 1.0000x reference)
#include <cuda_runtime.h>
#include <cstdint>
#include <cstddef>

// MPS chain contraction, B=256, N=128 -> 32768 independent elements.
// Each element: v(3) pushed through 221 matrices M_l = bias + sum_d x[l,d]*T[l,:,:,d].
//
// Strategy:
//  - 128 blocks x 128 threads, 2 elements per thread packed as f32x2 lane pairs.
//  - x data (90.8MB, per-element contiguous, 4B-aligned) is staged into smem via
//    coalesced 4B cp.async in 11 chunks of 21 steps (11*21=231 == element span),
//    double buffered. Layout [float_idx][thread] -> conflict-free LDS.64 reads.
//  - T (221*27 floats) staged once into smem DUPLICATED (t,t) so it is a native
//    f32x2 operand (broadcast LDS.64, no packing MOVs in the hot loop).
//  - All math in fma.rn.f32x2 / mul.rn.f32x2 (2 FLOPs per fma-pipe slot).

typedef unsigned long long u64;

#define NSTEPS      221
#define CH          21            // steps per chunk
#define NC          11            // chunks: 11*21 = 231 = full element span
#define FLO         63            // floats per chunk per element (CH*3)
#define BT          128           // threads per block
#define EPB         256           // elements per block (2 per thread)
#define NBLK        128           // 32768 / 256
#define ELEM_STRIDE 693           // 231*3 floats per element
#define T_ULL       5967          // 221*27 duplicated-pair T values

#define SMEM_ULL    (2 * FLO * BT + T_ULL)           // 16128 + 5967 = 22095
#define SMEM_BYTES  (SMEM_ULL * 8)                   // 176760 B

__device__ __forceinline__ u64 f2fma(u64 a, u64 b, u64 c) {
    u64 d; asm("fma.rn.f32x2 %0, %1, %2, %3;" : "=l"(d) : "l"(a), "l"(b), "l"(c)); return d;
}
__device__ __forceinline__ u64 f2mul(u64 a, u64 b) {
    u64 d; asm("mul.rn.f32x2 %0, %1, %2;" : "=l"(d) : "l"(a), "l"(b)); return d;
}
__device__ __forceinline__ u64 dup2(float v) {
    u64 d; asm("mov.b64 %0, {%1, %1};" : "=l"(d) : "f"(v)); return d;
}
__device__ __forceinline__ void unpack2(u64 v, float& lo, float& hi) {
    asm("mov.b64 {%0, %1}, %2;" : "=f"(lo), "=f"(hi) : "l"(v));
}
__device__ __forceinline__ void cpa4(uint32_t dst, const float* src) {
    asm volatile("cp.async.ca.shared.global [%0], [%1], 4;" :: "r"(dst), "l"(src) : "memory");
}
__device__ __forceinline__ void cpcommit() {
    asm volatile("cp.async.commit_group;" ::: "memory");
}
template <int N> __device__ __forceinline__ void cpwait() {
    asm volatile("cp.async.wait_group %0;" :: "n"(N) : "memory");
}

extern __shared__ u64 smem_u64[];

// Stage chunk c: elements [e0, e0+EPB), floats [c*FLO, c*FLO+FLO) of each element.
// Coalesced: linear index i walks each element's contiguous 63-float run.
// smem dst: pair index f*BT + (ee>>1), half (ee&1) -> (elemA, elemB) f32x2 pairs.
__device__ __forceinline__ void stage_chunk(const float* __restrict__ samples,
                                            int e0, int c, uint32_t sbase, int tid) {
    const float* src0 = samples + (size_t)e0 * ELEM_STRIDE + c * FLO;
    #pragma unroll 2
    for (int i = tid; i < EPB * FLO; i += BT) {
        int ee = i / FLO;
        int f  = i - ee * FLO;
        uint32_t dst = sbase + (uint32_t)((f * BT + (ee >> 1)) * 8 + (ee & 1) * 4);
        cpa4(dst, src0 + (size_t)ee * ELEM_STRIDE + f);
    }
    cpcommit();
}

__global__ void __launch_bounds__(BT, 1)
mps_kernel(const float* __restrict__ samples,
           const float* __restrict__ T1,
           const float* __restrict__ bias,
           float* __restrict__ out)
{
    const int tid = threadIdx.x;
    const int e0  = blockIdx.x * EPB;

    u64* xb0 = smem_u64;
    u64* xb1 = smem_u64 + FLO * BT;
    u64* Tsh = smem_u64 + 2 * FLO * BT;

    uint32_t xbase0 = (uint32_t)__cvta_generic_to_shared(xb0);
    uint32_t xbase1 = (uint32_t)__cvta_generic_to_shared(xb1);

    // Stage duplicated T: Tsh[i] = (T1[i], T1[i]) as an f32x2 operand.
    for (int i = tid; i < T_ULL; i += BT) {
        float v = T1[i];
        *reinterpret_cast<float2*>(&Tsh[i]) = make_float2(v, v);
    }

    // Bias pairs in registers (bias is [3,3], index l*3+r).
    u64 B[9];
    #pragma unroll
    for (int j = 0; j < 9; j++) B[j] = dup2(bias[j]);

    // Kick off chunk 0 while T staging settles.
    stage_chunk(samples, e0, 0, xbase0, tid);

    // v = (1, 0, 0) for both packed elements.
    u64 V0 = dup2(1.0f), V1 = dup2(0.0f), V2 = dup2(0.0f);

    for (int c = 0; c < NC; c++) {
        if (c + 1 < NC) {
            stage_chunk(samples, e0, c + 1, ((c + 1) & 1) ? xbase1 : xbase0, tid);
            cpwait<1>();            // chunk c complete, c+1 in flight
        } else {
            cpwait<0>();
        }
        __syncthreads();

        const u64* xr = ((c & 1) ? xb1 : xb0) + tid;   // stride BT per float slot
        const u64* Tr = Tsh + (size_t)c * CH * 27;
        const int nst = (c == NC - 1) ? (NSTEPS - (NC - 1) * CH) : CH;   // 11 on last

        #pragma unroll 3
        for (int ll = 0; ll < nst; ll++) {
            u64 X0 = xr[(ll * 3 + 0) * BT];
            u64 X1 = xr[(ll * 3 + 1) * BT];
            u64 X2 = xr[(ll * 3 + 2) * BT];
            const u64* tp = Tr + ll * 27;   // T[l][r][d] at l*9 + r*3 + d

            u64 n0, n1, n2;
            {   // r = 0
                u64 m0 = f2fma(X2, tp[2],  f2fma(X1, tp[1],  f2fma(X0, tp[0],  B[0])));
                u64 m1 = f2fma(X2, tp[11], f2fma(X1, tp[10], f2fma(X0, tp[9],  B[3])));
                u64 m2 = f2fma(X2, tp[20], f2fma(X1, tp[19], f2fma(X0, tp[18], B[6])));
                n0 = f2fma(V2, m2, f2fma(V1, m1, f2mul(V0, m0)));
            }
            {   // r = 1
                u64 m0 = f2fma(X2, tp[5],  f2fma(X1, tp[4],  f2fma(X0, tp[3],  B[1])));
                u64 m1 = f2fma(X2, tp[14], f2fma(X1, tp[13], f2fma(X0, tp[12], B[4])));
                u64 m2 = f2fma(X2, tp[23], f2fma(X1, tp[22], f2fma(X0, tp[21], B[7])));
                n1 = f2fma(V2, m2, f2fma(V1, m1, f2mul(V0, m0)));
            }
            {   // r = 2
                u64 m0 = f2fma(X2, tp[8],  f2fma(X1, tp[7],  f2fma(X0, tp[6],  B[2])));
                u64 m1 = f2fma(X2, tp[17], f2fma(X1, tp[16], f2fma(X0, tp[15], B[5])));
                u64 m2 = f2fma(X2, tp[26], f2fma(X1, tp[25], f2fma(X0, tp[24], B[8])));
                n2 = f2fma(V2, m2, f2fma(V1, m1, f2mul(V0, m0)));
            }
            V0 = n0; V1 = n1; V2 = n2;
        }
        __syncthreads();   // all readers of this buffer done before it is re-issued
    }

    // Write out: lo half = element 2*tid, hi half = element 2*tid+1.
    const int eA = e0 + 2 * tid;
    float a0, b0, a1, b1, a2, b2;
    unpack2(V0, a0, b0);
    unpack2(V1, a1, b1);
    unpack2(V2, a2, b2);
    float* oA = out + (size_t)eA * 3;
    oA[0] = a0; oA[1] = a1; oA[2] = a2;
    oA[3] = b0; oA[4] = b1; oA[5] = b2;
}

extern "C" void kernel_launch(void* const* d_in, const int* in_sizes, int n_in,
                              void* d_out, int out_size) {
    (void)in_sizes; (void)n_in; (void)out_size;
    const float* samples = (const float*)d_in[0];
    const float* tensors = (const float*)d_in[1];
    const float* bias    = (const float*)d_in[2];
    float* out = (float*)d_out;

    cudaFuncSetAttribute(mps_kernel, cudaFuncAttributeMaxDynamicSharedMemorySize, SMEM_BYTES);
    mps_kernel<<<NBLK, BT, SMEM_BYTES>>>(samples, tensors, bias, out);
}